// round 15
// baseline (speedup 1.0000x reference)
#include <cuda_runtime.h>
#include <cuda_fp16.h>
#include <cstdint>

// Block-causal attention, mma.sync fp16 (fp32 accumulate).
// Round-15: V is kept ROW-MAJOR fp16 and fed to GEMM2 via ldmatrix.x4.trans
// (flash-attn sm80 pattern) -> prep loses its transpose/sync/gather phase and
// becomes a pure streaming convert. Main kernel structure otherwise identical
// to round-14 (128 thr, 32 q-rows/warp, 3 CTA/SM, KSPLIT=4, cp.async
// double-buffer, ex2.f16x2 softmax, ones-fragment l-MMA, fp16 partials).

#define SEQ 2048
#define DH  64
#define QT  128
#define ST  64
#define PITCHB 144
#define KS  4

#define SM_Q    0
#define SM_KV0  (SM_Q + 128 * PITCHB)        // 18432
#define SM_KV1  (SM_KV0 + 128 * PITCHB)      // 36864
#define SM_TOTAL (SM_KV1 + 128 * PITCHB)     // 55296
#define KVBUF   (128 * PITCHB)
#define VOFF    (64 * PITCHB)

__device__ __half g_kh[8 * SEQ * DH];        // fp16 K [n][s][d]
__device__ __half g_vh[8 * SEQ * DH];        // fp16 V [n][s][d] (row-major!)
__device__ __half g_scr[KS][8 * SEQ * DH];   // fp16 partials
__device__ float  g_l[KS][8 * SEQ];

__device__ __forceinline__ uint32_t smem_u32(const void* p) {
    uint32_t a;
    asm("{ .reg .u64 t; cvta.to.shared.u64 t, %1; cvt.u32.u64 %0, t; }"
        : "=r"(a) : "l"(p));
    return a;
}
__device__ __forceinline__ void cp16(uint32_t smem, const __half* g) {
    asm volatile("cp.async.cg.shared.global [%0], [%1], 16;"
                 :: "r"(smem), "l"(__cvta_generic_to_global(g)) : "memory");
}
#define CP_COMMIT() asm volatile("cp.async.commit_group;" ::: "memory")
#define CP_WAIT0()  asm volatile("cp.async.wait_group 0;" ::: "memory")

#define LDSM_X4(r, a) \
    asm volatile("ldmatrix.sync.aligned.m8n8.x4.shared.b16 {%0,%1,%2,%3}, [%4];" \
        : "=r"((r)[0]), "=r"((r)[1]), "=r"((r)[2]), "=r"((r)[3]) : "r"(a))
#define LDSM_X4T(r, a) \
    asm volatile("ldmatrix.sync.aligned.m8n8.x4.trans.shared.b16 {%0,%1,%2,%3}, [%4];" \
        : "=r"((r)[0]), "=r"((r)[1]), "=r"((r)[2]), "=r"((r)[3]) : "r"(a))

__device__ __forceinline__ void mma_f16(float* c, const uint32_t* a, const uint32_t* b) {
    asm volatile(
        "mma.sync.aligned.m16n8k16.row.col.f32.f16.f16.f32 "
        "{%0,%1,%2,%3}, {%4,%5,%6,%7}, {%8,%9}, {%0,%1,%2,%3};"
        : "+f"(c[0]), "+f"(c[1]), "+f"(c[2]), "+f"(c[3])
        : "r"(a[0]), "r"(a[1]), "r"(a[2]), "r"(a[3]), "r"(b[0]), "r"(b[1]));
}
__device__ __forceinline__ uint32_t packh(__half a, __half b) {
    __half2 t; t.x = a; t.y = b;
    return *reinterpret_cast<uint32_t*>(&t);
}
__device__ __forceinline__ uint4 cvt8h(const float* x) {
    uint32_t h[4];
#pragma unroll
    for (int m = 0; m < 4; m++)
        h[m] = packh(__float2half_rn(x[2 * m]), __float2half_rn(x[2 * m + 1]));
    return make_uint4(h[0], h[1], h[2], h[3]);
}
__device__ __forceinline__ uint32_t exp2_pair(float lo, float hi) {
    uint32_t t;
    asm("cvt.rn.f16x2.f32 %0, %1, %2;" : "=r"(t) : "f"(hi), "f"(lo));
    asm("ex2.approx.f16x2 %0, %0;" : "+r"(t));
    return t;
}
__device__ __forceinline__ uint32_t pack2h(float a, float b) {
    uint32_t t;
    asm("cvt.rn.f16x2.f32 %0, %1, %2;" : "=r"(t) : "f"(b), "f"(a));
    return t;
}

// ---- pre-pass: K,V -> fp16 row-major (pure streaming convert, no smem) ----
// grid (32, 8): 64-row tiles; each thread: 2 K-chunks + 2 V-chunks (MLP 8).
__global__ __launch_bounds__(256)
void prep_kernel(const float* __restrict__ K, const float* __restrict__ V) {
    const int s0 = blockIdx.x * 64, n = blockIdx.y;
    const int tid = threadIdx.x;
#pragma unroll
    for (int gi = 0; gi < 2; gi++) {
        const int chunk = tid + 256 * gi;          // 0..511
        const int r = chunk >> 3, d8 = (chunk & 7) * 8;
        const size_t off = (size_t)(n * SEQ + s0 + r) * DH + d8;
        float x[8], y[8];
        *(float4*)&x[0] = *(const float4*)(K + off);
        *(float4*)&x[4] = *(const float4*)(K + off + 4);
        *(float4*)&y[0] = *(const float4*)(V + off);
        *(float4*)&y[4] = *(const float4*)(V + off + 4);
        *(uint4*)&g_kh[off] = cvt8h(x);
        *(uint4*)&g_vh[off] = cvt8h(y);
    }
}

__global__ __launch_bounds__(128, 3)
void attn_part_kernel(const float* __restrict__ Q, const int* __restrict__ prefix) {
    extern __shared__ char smem[];
    const uint32_t sb = smem_u32(smem);
    const int tid  = threadIdx.x;
    const int lane = tid & 31;
    const int w    = tid >> 5;           // 4 warps
    const int tg   = lane & 3;
    const int g    = lane >> 2;
    const int n    = blockIdx.y;
    const int qb   = blockIdx.x;
    const int sp   = blockIdx.z;
    const int q0   = qb * QT;
    const int P    = prefix[n];
    const int m0   = w * 32;             // 32 q-rows per warp (2 M-blocks)

    // ---- tile schedule ----
    const int T = (P + ST - 1) / ST;
    const int dA = qb * 2, dB = qb * 2 + 1;
    const int nPref = (T > sp) ? ((T - sp + 3) >> 2) : 0;
    const bool hasA = (dA >= T) && ((dA & (KS - 1)) == sp);
    const bool hasB = (dB >= T) && ((dB & (KS - 1)) == sp);
    const int nIter = nPref + (hasA ? 1 : 0) + (hasB ? 1 : 0);
    auto tile_of = [&](int it) -> int {
        if (it < nPref) return KS * it + sp;
        if (hasA && it == nPref) return dA;
        return dB;
    };

    auto issue_tile = [&](int t, int buf) {
        const int s0t = t * ST;
        const uint32_t kb = sb + SM_KV0 + buf * KVBUF;
        const uint32_t vb = kb + VOFF;
#pragma unroll
        for (int i = 0; i < 4; i++) {
            const int slot = tid + 128 * i;      // 0..511
            const int row = slot >> 3, c = slot & 7;
            const size_t off = (size_t)(n * SEQ + s0t + row) * DH + c * 8;
            cp16(kb + row * PITCHB + c * 16, &g_kh[off]);
            cp16(vb + row * PITCHB + c * 16, &g_vh[off]);
        }
        CP_COMMIT();
    };

    // prefetch tile 0 BEFORE Q staging (overlap gmem latency with Q convert)
    if (nIter > 0) issue_tile(tile_of(0), 0);

    // ---- Q tile -> smem fp16 (128 threads: 4 groups each) ----
#pragma unroll
    for (int gi = 0; gi < 4; gi++) {
        const int gg = tid + 128 * gi;
        const int r = gg >> 2, d8 = (gg & 3) * 16;
        float x[8];
        const float* qp = Q + (size_t)(n * SEQ + q0 + r) * DH + d8;
        *(float4*)&x[0] = *(const float4*)qp;
        *(float4*)&x[4] = *(const float4*)(qp + 4);
        *(uint4*)(smem + SM_Q + r * PITCHB + d8 * 2) = cvt8h(x);
        float y[8];
        *(float4*)&y[0] = *(const float4*)(qp + 8);
        *(float4*)&y[4] = *(const float4*)(qp + 12);
        *(uint4*)(smem + SM_Q + r * PITCHB + d8 * 2 + 16) = cvt8h(y);
    }
    __syncthreads();

    // ---- Q A-fragments: 2 M-blocks of 16 rows ----
    uint32_t qh[2][4][4];
#pragma unroll
    for (int mb = 0; mb < 2; mb++) {
        const uint32_t abase = sb + SM_Q + (m0 + mb * 16 + (lane & 15)) * PITCHB +
                               ((lane >> 4) & 1) * 16;
#pragma unroll
        for (int kk = 0; kk < 4; kk++) LDSM_X4(qh[mb][kk], abase + kk * 32);
    }

    float oacc[2][8][4], lacc[2][4];
#pragma unroll
    for (int mb = 0; mb < 2; mb++) {
#pragma unroll
        for (int j = 0; j < 8; j++)
#pragma unroll
            for (int e = 0; e < 4; e++) oacc[mb][j][e] = 0.0f;
#pragma unroll
        for (int e = 0; e < 4; e++) lacc[mb][e] = 0.0f;
    }

    // K (non-trans) B-fragment offset: rows = score n-dim (s), cols = k (d)
    const uint32_t boff =
        ((((lane >> 4) & 1) * 8 + (lane & 7)) * PITCHB) + ((lane >> 3) & 1) * 16;
    // V (trans) B-fragment offset: rows = k-dim (s), col-bytes = n (v)
    const uint32_t voff = (lane & 15) * PITCHB + ((lane >> 4) & 1) * 16;

    const uint32_t bone = (g == 0) ? 0x3C003C00u : 0u;
    const uint32_t bo[2] = { bone, bone };

    const float C = 0.18033688011112042f;   // log2(e)/8
    const int rA0 = q0 + m0 + g;            // mb=0 rows: rA0, rA0+8
    const int rA1 = rA0 + 16;               // mb=1 rows: rA1, rA1+8

    for (int it = 0; it < nIter; ++it) {
        const int s0 = tile_of(it) * ST;
        const int buf = it & 1;

        CP_WAIT0();
        __syncthreads();

        if (it + 1 < nIter) issue_tile(tile_of(it + 1), buf ^ 1);

        const uint32_t bK = sb + SM_KV0 + buf * KVBUF + boff;
        const uint32_t bV = sb + SM_KV0 + buf * KVBUF + VOFF + voff;
        const bool interior = (s0 + ST <= P);

#pragma unroll
        for (int jp = 0; jp < 4; jp++) {
            // ---- GEMM1 chunk: 16 score columns x 32 rows ----
            float sc[2][2][4];
#pragma unroll
            for (int mb = 0; mb < 2; mb++)
#pragma unroll
                for (int h = 0; h < 2; h++)
#pragma unroll
                    for (int e = 0; e < 4; e++) sc[mb][h][e] = 0.0f;
            const uint32_t ka = bK + jp * (16 * PITCHB);
#pragma unroll
            for (int kk = 0; kk < 4; kk++) {
                uint32_t bh[4];
                LDSM_X4(bh, ka + kk * 32);
                mma_f16(sc[0][0], qh[0][kk], bh);
                mma_f16(sc[1][0], qh[1][kk], bh);
                mma_f16(sc[0][1], qh[0][kk], bh + 2);
                mma_f16(sc[1][1], qh[1][kk], bh + 2);
            }

            // ---- softmax chunk -> P fragments (both M-blocks) ----
            uint32_t af[2][4];
            if (interior) {
#pragma unroll
                for (int mb = 0; mb < 2; mb++) {
                    af[mb][0] = exp2_pair(sc[mb][0][0] * C, sc[mb][0][1] * C);
                    af[mb][1] = exp2_pair(sc[mb][0][2] * C, sc[mb][0][3] * C);
                    af[mb][2] = exp2_pair(sc[mb][1][0] * C, sc[mb][1][1] * C);
                    af[mb][3] = exp2_pair(sc[mb][1][2] * C, sc[mb][1][3] * C);
                }
            } else {
                const int cb0 = s0 + (2 * jp) * 8 + tg * 2;
                const int cb1 = cb0 + 8;
                const bool p00 = (cb0 < P),     p01 = (cb0 + 1 < P);
                const bool p10 = (cb1 < P),     p11 = (cb1 + 1 < P);
#pragma unroll
                for (int mb = 0; mb < 2; mb++) {
                    const int ra = (mb == 0) ? rA0 : rA1;
                    const int rb = ra + 8;
                    const float a0 = (p00 || cb0 == ra)     ? sc[mb][0][0] * C : -1e30f;
                    const float a1 = (p01 || cb0 + 1 == ra) ? sc[mb][0][1] * C : -1e30f;
                    const float a2 = (p00 || cb0 == rb)     ? sc[mb][0][2] * C : -1e30f;
                    const float a3 = (p01 || cb0 + 1 == rb) ? sc[mb][0][3] * C : -1e30f;
                    af[mb][0] = exp2_pair(a0, a1);
                    af[mb][1] = exp2_pair(a2, a3);
                    const float b0 = (p10 || cb1 == ra)     ? sc[mb][1][0] * C : -1e30f;
                    const float b1 = (p11 || cb1 + 1 == ra) ? sc[mb][1][1] * C : -1e30f;
                    const float b2 = (p10 || cb1 == rb)     ? sc[mb][1][2] * C : -1e30f;
                    const float b3 = (p11 || cb1 + 1 == rb) ? sc[mb][1][3] * C : -1e30f;
                    af[mb][2] = exp2_pair(b0, b1);
                    af[mb][3] = exp2_pair(b2, b3);
                }
            }

            // ---- GEMM2 chunk: O += P @ V; l += P @ ones ----
            mma_f16(lacc[0], af[0], bo);
            mma_f16(lacc[1], af[1], bo);
#pragma unroll
            for (int jp2 = 0; jp2 < 4; jp2++) {
                // trans-LDSM: rows = s (this jp chunk), col-bytes = v (jp2)
                const uint32_t va = bV + jp * (16 * PITCHB) + jp2 * 32;
                uint32_t vh[4];
                LDSM_X4T(vh, va);
                mma_f16(oacc[0][2 * jp2],     af[0], vh);
                mma_f16(oacc[1][2 * jp2],     af[1], vh);
                mma_f16(oacc[0][2 * jp2 + 1], af[0], vh + 2);
                mma_f16(oacc[1][2 * jp2 + 1], af[1], vh + 2);
            }
        }
    }

    // ---- write fp16 partials + fp32 l (4 rows per thread) ----
    if (tg == 0) {
        g_l[sp][n * SEQ + rA0]     = lacc[0][0];
        g_l[sp][n * SEQ + rA0 + 8] = lacc[0][2];
        g_l[sp][n * SEQ + rA1]     = lacc[1][0];
        g_l[sp][n * SEQ + rA1 + 8] = lacc[1][2];
    }
    __half* scr = g_scr[sp];
#pragma unroll
    for (int mb = 0; mb < 2; mb++) {
        const int ra = (mb == 0) ? rA0 : rA1;
#pragma unroll
        for (int j = 0; j < 8; j++) {
            const int col = j * 8 + tg * 2;
            *(uint32_t*)(scr + (size_t)(n * SEQ + ra) * DH + col) =
                pack2h(oacc[mb][j][0], oacc[mb][j][1]);
            *(uint32_t*)(scr + (size_t)(n * SEQ + ra + 8) * DH + col) =
                pack2h(oacc[mb][j][2], oacc[mb][j][3]);
        }
    }
}

__global__ __launch_bounds__(256, 8)
void combine_kernel(float* __restrict__ O) {
    const int i = blockIdx.x * 256 + threadIdx.x;   // float4 index, 262144 total
    const int row = i >> 4;
    float l = 0.0f;
    float4 a = make_float4(0.f, 0.f, 0.f, 0.f);
#pragma unroll
    for (int s = 0; s < KS; s++) {
        const uint2 u = ((const uint2*)g_scr[s])[i];
        const __half2 p0 = *reinterpret_cast<const __half2*>(&u.x);
        const __half2 p1 = *reinterpret_cast<const __half2*>(&u.y);
        a.x += __low2float(p0);  a.y += __high2float(p0);
        a.z += __low2float(p1);  a.w += __high2float(p1);
        l += g_l[s][row];
    }
    const float inv = 1.0f / l;
    ((float4*)O)[i] = make_float4(a.x * inv, a.y * inv, a.z * inv, a.w * inv);
}

extern "C" void kernel_launch(void* const* d_in, const int* in_sizes, int n_in,
                              void* d_out, int out_size) {
    const float* Q      = (const float*)d_in[0];
    const float* K      = (const float*)d_in[1];
    const float* V      = (const float*)d_in[2];
    const int*   prefix = (const int*)d_in[3];
    float*       O      = (float*)d_out;

    prep_kernel<<<dim3(32, 8), 256>>>(K, V);
    cudaFuncSetAttribute(attn_part_kernel,
                         cudaFuncAttributeMaxDynamicSharedMemorySize, SM_TOTAL);
    attn_part_kernel<<<dim3(16, 8, KS), 128, SM_TOTAL>>>(Q, prefix);
    combine_kernel<<<(8 * SEQ * DH / 4) / 256, 256>>>(O);
}

// round 16
// speedup vs baseline: 1.0010x; 1.0010x over previous
#include <cuda_runtime.h>
#include <cuda_fp16.h>
#include <cstdint>

// Block-causal attention, mma.sync fp16 (fp32 accumulate).
// Round-16: prep re-gridded for latency-bound regime (128x8 CTAs x 128 thr,
// 1 chunk/thread); combine does 2 same-row groups/thread (l loaded once).
// Main kernel unchanged from round-15 (128 thr, 32 q-rows/warp, 3 CTA/SM,
// KSPLIT=4, cp.async double-buffer, trans-LDSM V, ex2.f16x2 softmax,
// ones-fragment l-MMA, fp16 partials).

#define SEQ 2048
#define DH  64
#define QT  128
#define ST  64
#define PITCHB 144
#define KS  4

#define SM_Q    0
#define SM_KV0  (SM_Q + 128 * PITCHB)        // 18432
#define SM_KV1  (SM_KV0 + 128 * PITCHB)      // 36864
#define SM_TOTAL (SM_KV1 + 128 * PITCHB)     // 55296
#define KVBUF   (128 * PITCHB)
#define VOFF    (64 * PITCHB)

__device__ __half g_kh[8 * SEQ * DH];        // fp16 K [n][s][d]
__device__ __half g_vh[8 * SEQ * DH];        // fp16 V [n][s][d] (row-major)
__device__ __half g_scr[KS][8 * SEQ * DH];   // fp16 partials
__device__ float  g_l[KS][8 * SEQ];

__device__ __forceinline__ uint32_t smem_u32(const void* p) {
    uint32_t a;
    asm("{ .reg .u64 t; cvta.to.shared.u64 t, %1; cvt.u32.u64 %0, t; }"
        : "=r"(a) : "l"(p));
    return a;
}
__device__ __forceinline__ void cp16(uint32_t smem, const __half* g) {
    asm volatile("cp.async.cg.shared.global [%0], [%1], 16;"
                 :: "r"(smem), "l"(__cvta_generic_to_global(g)) : "memory");
}
#define CP_COMMIT() asm volatile("cp.async.commit_group;" ::: "memory")
#define CP_WAIT0()  asm volatile("cp.async.wait_group 0;" ::: "memory")

#define LDSM_X4(r, a) \
    asm volatile("ldmatrix.sync.aligned.m8n8.x4.shared.b16 {%0,%1,%2,%3}, [%4];" \
        : "=r"((r)[0]), "=r"((r)[1]), "=r"((r)[2]), "=r"((r)[3]) : "r"(a))
#define LDSM_X4T(r, a) \
    asm volatile("ldmatrix.sync.aligned.m8n8.x4.trans.shared.b16 {%0,%1,%2,%3}, [%4];" \
        : "=r"((r)[0]), "=r"((r)[1]), "=r"((r)[2]), "=r"((r)[3]) : "r"(a))

__device__ __forceinline__ void mma_f16(float* c, const uint32_t* a, const uint32_t* b) {
    asm volatile(
        "mma.sync.aligned.m16n8k16.row.col.f32.f16.f16.f32 "
        "{%0,%1,%2,%3}, {%4,%5,%6,%7}, {%8,%9}, {%0,%1,%2,%3};"
        : "+f"(c[0]), "+f"(c[1]), "+f"(c[2]), "+f"(c[3])
        : "r"(a[0]), "r"(a[1]), "r"(a[2]), "r"(a[3]), "r"(b[0]), "r"(b[1]));
}
__device__ __forceinline__ uint32_t packh(__half a, __half b) {
    __half2 t; t.x = a; t.y = b;
    return *reinterpret_cast<uint32_t*>(&t);
}
__device__ __forceinline__ uint4 cvt8h(const float* x) {
    uint32_t h[4];
#pragma unroll
    for (int m = 0; m < 4; m++)
        h[m] = packh(__float2half_rn(x[2 * m]), __float2half_rn(x[2 * m + 1]));
    return make_uint4(h[0], h[1], h[2], h[3]);
}
__device__ __forceinline__ uint32_t exp2_pair(float lo, float hi) {
    uint32_t t;
    asm("cvt.rn.f16x2.f32 %0, %1, %2;" : "=r"(t) : "f"(hi), "f"(lo));
    asm("ex2.approx.f16x2 %0, %0;" : "+r"(t));
    return t;
}
__device__ __forceinline__ uint32_t pack2h(float a, float b) {
    uint32_t t;
    asm("cvt.rn.f16x2.f32 %0, %1, %2;" : "=r"(t) : "f"(b), "f"(a));
    return t;
}

// ---- pre-pass: K,V -> fp16 row-major. Latency-bound regime: 1 chunk per
// thread, 131072 threads (grid 128x8, 128 thr). 8 independent loads each. ----
__global__ __launch_bounds__(128)
void prep_kernel(const float* __restrict__ K, const float* __restrict__ V) {
    const int n = blockIdx.y;
    const int chunk = blockIdx.x * 128 + threadIdx.x;   // 0..16383 per batch
    const int r = chunk >> 3, d8 = (chunk & 7) * 8;
    const size_t off = (size_t)(n * SEQ + r) * DH + d8;
    float x[8], y[8];
    *(float4*)&x[0] = *(const float4*)(K + off);
    *(float4*)&x[4] = *(const float4*)(K + off + 4);
    *(float4*)&y[0] = *(const float4*)(V + off);
    *(float4*)&y[4] = *(const float4*)(V + off + 4);
    *(uint4*)&g_kh[off] = cvt8h(x);
    *(uint4*)&g_vh[off] = cvt8h(y);
}

__global__ __launch_bounds__(128, 3)
void attn_part_kernel(const float* __restrict__ Q, const int* __restrict__ prefix) {
    extern __shared__ char smem[];
    const uint32_t sb = smem_u32(smem);
    const int tid  = threadIdx.x;
    const int lane = tid & 31;
    const int w    = tid >> 5;           // 4 warps
    const int tg   = lane & 3;
    const int g    = lane >> 2;
    const int n    = blockIdx.y;
    const int qb   = blockIdx.x;
    const int sp   = blockIdx.z;
    const int q0   = qb * QT;
    const int P    = prefix[n];
    const int m0   = w * 32;             // 32 q-rows per warp (2 M-blocks)

    // ---- tile schedule ----
    const int T = (P + ST - 1) / ST;
    const int dA = qb * 2, dB = qb * 2 + 1;
    const int nPref = (T > sp) ? ((T - sp + 3) >> 2) : 0;
    const bool hasA = (dA >= T) && ((dA & (KS - 1)) == sp);
    const bool hasB = (dB >= T) && ((dB & (KS - 1)) == sp);
    const int nIter = nPref + (hasA ? 1 : 0) + (hasB ? 1 : 0);
    auto tile_of = [&](int it) -> int {
        if (it < nPref) return KS * it + sp;
        if (hasA && it == nPref) return dA;
        return dB;
    };

    auto issue_tile = [&](int t, int buf) {
        const int s0t = t * ST;
        const uint32_t kb = sb + SM_KV0 + buf * KVBUF;
        const uint32_t vb = kb + VOFF;
#pragma unroll
        for (int i = 0; i < 4; i++) {
            const int slot = tid + 128 * i;      // 0..511
            const int row = slot >> 3, c = slot & 7;
            const size_t off = (size_t)(n * SEQ + s0t + row) * DH + c * 8;
            cp16(kb + row * PITCHB + c * 16, &g_kh[off]);
            cp16(vb + row * PITCHB + c * 16, &g_vh[off]);
        }
        CP_COMMIT();
    };

    // prefetch tile 0 BEFORE Q staging (overlap gmem latency with Q convert)
    if (nIter > 0) issue_tile(tile_of(0), 0);

    // ---- Q tile -> smem fp16 (128 threads: 4 groups each) ----
#pragma unroll
    for (int gi = 0; gi < 4; gi++) {
        const int gg = tid + 128 * gi;
        const int r = gg >> 2, d8 = (gg & 3) * 16;
        float x[8];
        const float* qp = Q + (size_t)(n * SEQ + q0 + r) * DH + d8;
        *(float4*)&x[0] = *(const float4*)qp;
        *(float4*)&x[4] = *(const float4*)(qp + 4);
        *(uint4*)(smem + SM_Q + r * PITCHB + d8 * 2) = cvt8h(x);
        float y[8];
        *(float4*)&y[0] = *(const float4*)(qp + 8);
        *(float4*)&y[4] = *(const float4*)(qp + 12);
        *(uint4*)(smem + SM_Q + r * PITCHB + d8 * 2 + 16) = cvt8h(y);
    }
    __syncthreads();

    // ---- Q A-fragments: 2 M-blocks of 16 rows ----
    uint32_t qh[2][4][4];
#pragma unroll
    for (int mb = 0; mb < 2; mb++) {
        const uint32_t abase = sb + SM_Q + (m0 + mb * 16 + (lane & 15)) * PITCHB +
                               ((lane >> 4) & 1) * 16;
#pragma unroll
        for (int kk = 0; kk < 4; kk++) LDSM_X4(qh[mb][kk], abase + kk * 32);
    }

    float oacc[2][8][4], lacc[2][4];
#pragma unroll
    for (int mb = 0; mb < 2; mb++) {
#pragma unroll
        for (int j = 0; j < 8; j++)
#pragma unroll
            for (int e = 0; e < 4; e++) oacc[mb][j][e] = 0.0f;
#pragma unroll
        for (int e = 0; e < 4; e++) lacc[mb][e] = 0.0f;
    }

    // K (non-trans) B-fragment offset: rows = score n-dim (s), cols = k (d)
    const uint32_t boff =
        ((((lane >> 4) & 1) * 8 + (lane & 7)) * PITCHB) + ((lane >> 3) & 1) * 16;
    // V (trans) B-fragment offset: rows = k-dim (s), col-bytes = n (v)
    const uint32_t voff = (lane & 15) * PITCHB + ((lane >> 4) & 1) * 16;

    const uint32_t bone = (g == 0) ? 0x3C003C00u : 0u;
    const uint32_t bo[2] = { bone, bone };

    const float C = 0.18033688011112042f;   // log2(e)/8
    const int rA0 = q0 + m0 + g;            // mb=0 rows: rA0, rA0+8
    const int rA1 = rA0 + 16;               // mb=1 rows: rA1, rA1+8

    for (int it = 0; it < nIter; ++it) {
        const int s0 = tile_of(it) * ST;
        const int buf = it & 1;

        CP_WAIT0();
        __syncthreads();

        if (it + 1 < nIter) issue_tile(tile_of(it + 1), buf ^ 1);

        const uint32_t bK = sb + SM_KV0 + buf * KVBUF + boff;
        const uint32_t bV = sb + SM_KV0 + buf * KVBUF + VOFF + voff;
        const bool interior = (s0 + ST <= P);

#pragma unroll
        for (int jp = 0; jp < 4; jp++) {
            // ---- GEMM1 chunk: 16 score columns x 32 rows ----
            float sc[2][2][4];
#pragma unroll
            for (int mb = 0; mb < 2; mb++)
#pragma unroll
                for (int h = 0; h < 2; h++)
#pragma unroll
                    for (int e = 0; e < 4; e++) sc[mb][h][e] = 0.0f;
            const uint32_t ka = bK + jp * (16 * PITCHB);
#pragma unroll
            for (int kk = 0; kk < 4; kk++) {
                uint32_t bh[4];
                LDSM_X4(bh, ka + kk * 32);
                mma_f16(sc[0][0], qh[0][kk], bh);
                mma_f16(sc[1][0], qh[1][kk], bh);
                mma_f16(sc[0][1], qh[0][kk], bh + 2);
                mma_f16(sc[1][1], qh[1][kk], bh + 2);
            }

            // ---- softmax chunk -> P fragments (both M-blocks) ----
            uint32_t af[2][4];
            if (interior) {
#pragma unroll
                for (int mb = 0; mb < 2; mb++) {
                    af[mb][0] = exp2_pair(sc[mb][0][0] * C, sc[mb][0][1] * C);
                    af[mb][1] = exp2_pair(sc[mb][0][2] * C, sc[mb][0][3] * C);
                    af[mb][2] = exp2_pair(sc[mb][1][0] * C, sc[mb][1][1] * C);
                    af[mb][3] = exp2_pair(sc[mb][1][2] * C, sc[mb][1][3] * C);
                }
            } else {
                const int cb0 = s0 + (2 * jp) * 8 + tg * 2;
                const int cb1 = cb0 + 8;
                const bool p00 = (cb0 < P),     p01 = (cb0 + 1 < P);
                const bool p10 = (cb1 < P),     p11 = (cb1 + 1 < P);
#pragma unroll
                for (int mb = 0; mb < 2; mb++) {
                    const int ra = (mb == 0) ? rA0 : rA1;
                    const int rb = ra + 8;
                    const float a0 = (p00 || cb0 == ra)     ? sc[mb][0][0] * C : -1e30f;
                    const float a1 = (p01 || cb0 + 1 == ra) ? sc[mb][0][1] * C : -1e30f;
                    const float a2 = (p00 || cb0 == rb)     ? sc[mb][0][2] * C : -1e30f;
                    const float a3 = (p01 || cb0 + 1 == rb) ? sc[mb][0][3] * C : -1e30f;
                    af[mb][0] = exp2_pair(a0, a1);
                    af[mb][1] = exp2_pair(a2, a3);
                    const float b0 = (p10 || cb1 == ra)     ? sc[mb][1][0] * C : -1e30f;
                    const float b1 = (p11 || cb1 + 1 == ra) ? sc[mb][1][1] * C : -1e30f;
                    const float b2 = (p10 || cb1 == rb)     ? sc[mb][1][2] * C : -1e30f;
                    const float b3 = (p11 || cb1 + 1 == rb) ? sc[mb][1][3] * C : -1e30f;
                    af[mb][2] = exp2_pair(b0, b1);
                    af[mb][3] = exp2_pair(b2, b3);
                }
            }

            // ---- GEMM2 chunk: O += P @ V; l += P @ ones ----
            mma_f16(lacc[0], af[0], bo);
            mma_f16(lacc[1], af[1], bo);
#pragma unroll
            for (int jp2 = 0; jp2 < 4; jp2++) {
                const uint32_t va = bV + jp * (16 * PITCHB) + jp2 * 32;
                uint32_t vh[4];
                LDSM_X4T(vh, va);
                mma_f16(oacc[0][2 * jp2],     af[0], vh);
                mma_f16(oacc[1][2 * jp2],     af[1], vh);
                mma_f16(oacc[0][2 * jp2 + 1], af[0], vh + 2);
                mma_f16(oacc[1][2 * jp2 + 1], af[1], vh + 2);
            }
        }
    }

    // ---- write fp16 partials + fp32 l (4 rows per thread) ----
    if (tg == 0) {
        g_l[sp][n * SEQ + rA0]     = lacc[0][0];
        g_l[sp][n * SEQ + rA0 + 8] = lacc[0][2];
        g_l[sp][n * SEQ + rA1]     = lacc[1][0];
        g_l[sp][n * SEQ + rA1 + 8] = lacc[1][2];
    }
    __half* scr = g_scr[sp];
#pragma unroll
    for (int mb = 0; mb < 2; mb++) {
        const int ra = (mb == 0) ? rA0 : rA1;
#pragma unroll
        for (int j = 0; j < 8; j++) {
            const int col = j * 8 + tg * 2;
            *(uint32_t*)(scr + (size_t)(n * SEQ + ra) * DH + col) =
                pack2h(oacc[mb][j][0], oacc[mb][j][1]);
            *(uint32_t*)(scr + (size_t)(n * SEQ + ra + 8) * DH + col) =
                pack2h(oacc[mb][j][2], oacc[mb][j][3]);
        }
    }
}

// ---- combine: 2 same-row float4 groups per thread; l loaded once ----
__global__ __launch_bounds__(256, 8)
void combine_kernel(float* __restrict__ O) {
    const int t = blockIdx.x * 256 + threadIdx.x;   // 0..131071
    const int i0 = t * 2;                           // float4 group pair (same row)
    const int row = i0 >> 4;
    float l = 0.0f;
    float4 a = make_float4(0.f, 0.f, 0.f, 0.f);
    float4 b = make_float4(0.f, 0.f, 0.f, 0.f);
#pragma unroll
    for (int s = 0; s < KS; s++) {
        const uint4 u = *(const uint4*)&((const uint2*)g_scr[s])[i0];
        const __half2 p0 = *reinterpret_cast<const __half2*>(&u.x);
        const __half2 p1 = *reinterpret_cast<const __half2*>(&u.y);
        const __half2 p2 = *reinterpret_cast<const __half2*>(&u.z);
        const __half2 p3 = *reinterpret_cast<const __half2*>(&u.w);
        a.x += __low2float(p0);  a.y += __high2float(p0);
        a.z += __low2float(p1);  a.w += __high2float(p1);
        b.x += __low2float(p2);  b.y += __high2float(p2);
        b.z += __low2float(p3);  b.w += __high2float(p3);
        l += g_l[s][row];
    }
    const float inv = 1.0f / l;
    ((float4*)O)[i0]     = make_float4(a.x * inv, a.y * inv, a.z * inv, a.w * inv);
    ((float4*)O)[i0 + 1] = make_float4(b.x * inv, b.y * inv, b.z * inv, b.w * inv);
}

extern "C" void kernel_launch(void* const* d_in, const int* in_sizes, int n_in,
                              void* d_out, int out_size) {
    const float* Q      = (const float*)d_in[0];
    const float* K      = (const float*)d_in[1];
    const float* V      = (const float*)d_in[2];
    const int*   prefix = (const int*)d_in[3];
    float*       O      = (float*)d_out;

    prep_kernel<<<dim3(128, 8), 128>>>(K, V);
    cudaFuncSetAttribute(attn_part_kernel,
                         cudaFuncAttributeMaxDynamicSharedMemorySize, SM_TOTAL);
    attn_part_kernel<<<dim3(16, 8, KS), 128, SM_TOTAL>>>(Q, prefix);
    combine_kernel<<<(8 * SEQ * DH / 8) / 256, 256>>>(O);
}

// round 17
// speedup vs baseline: 1.0051x; 1.0041x over previous
#include <cuda_runtime.h>
#include <cuda_fp16.h>
#include <cstdint>

// Block-causal attention, mma.sync fp16 (fp32 accumulate).
// Round-17: batch-interleaved 1D grid for the main kernel (n fastest) so
// each SM's co-resident CTAs mix prefix lengths -> SM load balance.
// Otherwise identical to round-16 (128 thr, 32 q-rows/warp, 3 CTA/SM,
// KSPLIT=4, cp.async double-buffer, trans-LDSM V, ex2.f16x2 softmax,
// ones-fragment l-MMA, fp16 partials, streaming prep).

#define SEQ 2048
#define DH  64
#define QT  128
#define ST  64
#define PITCHB 144
#define KS  4

#define SM_Q    0
#define SM_KV0  (SM_Q + 128 * PITCHB)        // 18432
#define SM_KV1  (SM_KV0 + 128 * PITCHB)      // 36864
#define SM_TOTAL (SM_KV1 + 128 * PITCHB)     // 55296
#define KVBUF   (128 * PITCHB)
#define VOFF    (64 * PITCHB)

__device__ __half g_kh[8 * SEQ * DH];        // fp16 K [n][s][d]
__device__ __half g_vh[8 * SEQ * DH];        // fp16 V [n][s][d] (row-major)
__device__ __half g_scr[KS][8 * SEQ * DH];   // fp16 partials
__device__ float  g_l[KS][8 * SEQ];

__device__ __forceinline__ uint32_t smem_u32(const void* p) {
    uint32_t a;
    asm("{ .reg .u64 t; cvta.to.shared.u64 t, %1; cvt.u32.u64 %0, t; }"
        : "=r"(a) : "l"(p));
    return a;
}
__device__ __forceinline__ void cp16(uint32_t smem, const __half* g) {
    asm volatile("cp.async.cg.shared.global [%0], [%1], 16;"
                 :: "r"(smem), "l"(__cvta_generic_to_global(g)) : "memory");
}
#define CP_COMMIT() asm volatile("cp.async.commit_group;" ::: "memory")
#define CP_WAIT0()  asm volatile("cp.async.wait_group 0;" ::: "memory")

#define LDSM_X4(r, a) \
    asm volatile("ldmatrix.sync.aligned.m8n8.x4.shared.b16 {%0,%1,%2,%3}, [%4];" \
        : "=r"((r)[0]), "=r"((r)[1]), "=r"((r)[2]), "=r"((r)[3]) : "r"(a))
#define LDSM_X4T(r, a) \
    asm volatile("ldmatrix.sync.aligned.m8n8.x4.trans.shared.b16 {%0,%1,%2,%3}, [%4];" \
        : "=r"((r)[0]), "=r"((r)[1]), "=r"((r)[2]), "=r"((r)[3]) : "r"(a))

__device__ __forceinline__ void mma_f16(float* c, const uint32_t* a, const uint32_t* b) {
    asm volatile(
        "mma.sync.aligned.m16n8k16.row.col.f32.f16.f16.f32 "
        "{%0,%1,%2,%3}, {%4,%5,%6,%7}, {%8,%9}, {%0,%1,%2,%3};"
        : "+f"(c[0]), "+f"(c[1]), "+f"(c[2]), "+f"(c[3])
        : "r"(a[0]), "r"(a[1]), "r"(a[2]), "r"(a[3]), "r"(b[0]), "r"(b[1]));
}
__device__ __forceinline__ uint32_t packh(__half a, __half b) {
    __half2 t; t.x = a; t.y = b;
    return *reinterpret_cast<uint32_t*>(&t);
}
__device__ __forceinline__ uint4 cvt8h(const float* x) {
    uint32_t h[4];
#pragma unroll
    for (int m = 0; m < 4; m++)
        h[m] = packh(__float2half_rn(x[2 * m]), __float2half_rn(x[2 * m + 1]));
    return make_uint4(h[0], h[1], h[2], h[3]);
}
__device__ __forceinline__ uint32_t exp2_pair(float lo, float hi) {
    uint32_t t;
    asm("cvt.rn.f16x2.f32 %0, %1, %2;" : "=r"(t) : "f"(hi), "f"(lo));
    asm("ex2.approx.f16x2 %0, %0;" : "+r"(t));
    return t;
}
__device__ __forceinline__ uint32_t pack2h(float a, float b) {
    uint32_t t;
    asm("cvt.rn.f16x2.f32 %0, %1, %2;" : "=r"(t) : "f"(b), "f"(a));
    return t;
}

// ---- pre-pass: K,V -> fp16 row-major (pure streaming convert) ----
__global__ __launch_bounds__(128)
void prep_kernel(const float* __restrict__ K, const float* __restrict__ V) {
    const int n = blockIdx.y;
    const int chunk = blockIdx.x * 128 + threadIdx.x;   // 0..16383 per batch
    const int r = chunk >> 3, d8 = (chunk & 7) * 8;
    const size_t off = (size_t)(n * SEQ + r) * DH + d8;
    float x[8], y[8];
    *(float4*)&x[0] = *(const float4*)(K + off);
    *(float4*)&x[4] = *(const float4*)(K + off + 4);
    *(float4*)&y[0] = *(const float4*)(V + off);
    *(float4*)&y[4] = *(const float4*)(V + off + 4);
    *(uint4*)&g_kh[off] = cvt8h(x);
    *(uint4*)&g_vh[off] = cvt8h(y);
}

__global__ __launch_bounds__(128, 3)
void attn_part_kernel(const float* __restrict__ Q, const int* __restrict__ prefix) {
    extern __shared__ char smem[];
    const uint32_t sb = smem_u32(smem);
    const int tid  = threadIdx.x;
    const int lane = tid & 31;
    const int w    = tid >> 5;           // 4 warps
    const int tg   = lane & 3;
    const int g    = lane >> 2;
    // batch-interleaved decode: n fastest -> SM-co-resident CTAs mix batches
    const int bid  = blockIdx.x;
    const int n    = bid & 7;
    const int qb   = (bid >> 3) & 15;
    const int sp   = bid >> 7;
    const int q0   = qb * QT;
    const int P    = prefix[n];
    const int m0   = w * 32;             // 32 q-rows per warp (2 M-blocks)

    // ---- tile schedule ----
    const int T = (P + ST - 1) / ST;
    const int dA = qb * 2, dB = qb * 2 + 1;
    const int nPref = (T > sp) ? ((T - sp + 3) >> 2) : 0;
    const bool hasA = (dA >= T) && ((dA & (KS - 1)) == sp);
    const bool hasB = (dB >= T) && ((dB & (KS - 1)) == sp);
    const int nIter = nPref + (hasA ? 1 : 0) + (hasB ? 1 : 0);
    auto tile_of = [&](int it) -> int {
        if (it < nPref) return KS * it + sp;
        if (hasA && it == nPref) return dA;
        return dB;
    };

    auto issue_tile = [&](int t, int buf) {
        const int s0t = t * ST;
        const uint32_t kb = sb + SM_KV0 + buf * KVBUF;
        const uint32_t vb = kb + VOFF;
#pragma unroll
        for (int i = 0; i < 4; i++) {
            const int slot = tid + 128 * i;      // 0..511
            const int row = slot >> 3, c = slot & 7;
            const size_t off = (size_t)(n * SEQ + s0t + row) * DH + c * 8;
            cp16(kb + row * PITCHB + c * 16, &g_kh[off]);
            cp16(vb + row * PITCHB + c * 16, &g_vh[off]);
        }
        CP_COMMIT();
    };

    // prefetch tile 0 BEFORE Q staging (overlap gmem latency with Q convert)
    if (nIter > 0) issue_tile(tile_of(0), 0);

    // ---- Q tile -> smem fp16 (128 threads: 4 groups each) ----
#pragma unroll
    for (int gi = 0; gi < 4; gi++) {
        const int gg = tid + 128 * gi;
        const int r = gg >> 2, d8 = (gg & 3) * 16;
        float x[8];
        const float* qp = Q + (size_t)(n * SEQ + q0 + r) * DH + d8;
        *(float4*)&x[0] = *(const float4*)qp;
        *(float4*)&x[4] = *(const float4*)(qp + 4);
        *(uint4*)(smem + SM_Q + r * PITCHB + d8 * 2) = cvt8h(x);
        float y[8];
        *(float4*)&y[0] = *(const float4*)(qp + 8);
        *(float4*)&y[4] = *(const float4*)(qp + 12);
        *(uint4*)(smem + SM_Q + r * PITCHB + d8 * 2 + 16) = cvt8h(y);
    }
    __syncthreads();

    // ---- Q A-fragments: 2 M-blocks of 16 rows ----
    uint32_t qh[2][4][4];
#pragma unroll
    for (int mb = 0; mb < 2; mb++) {
        const uint32_t abase = sb + SM_Q + (m0 + mb * 16 + (lane & 15)) * PITCHB +
                               ((lane >> 4) & 1) * 16;
#pragma unroll
        for (int kk = 0; kk < 4; kk++) LDSM_X4(qh[mb][kk], abase + kk * 32);
    }

    float oacc[2][8][4], lacc[2][4];
#pragma unroll
    for (int mb = 0; mb < 2; mb++) {
#pragma unroll
        for (int j = 0; j < 8; j++)
#pragma unroll
            for (int e = 0; e < 4; e++) oacc[mb][j][e] = 0.0f;
#pragma unroll
        for (int e = 0; e < 4; e++) lacc[mb][e] = 0.0f;
    }

    // K (non-trans) B-fragment offset: rows = score n-dim (s), cols = k (d)
    const uint32_t boff =
        ((((lane >> 4) & 1) * 8 + (lane & 7)) * PITCHB) + ((lane >> 3) & 1) * 16;
    // V (trans) B-fragment offset: rows = k-dim (s), col-bytes = n (v)
    const uint32_t voff = (lane & 15) * PITCHB + ((lane >> 4) & 1) * 16;

    const uint32_t bone = (g == 0) ? 0x3C003C00u : 0u;
    const uint32_t bo[2] = { bone, bone };

    const float C = 0.18033688011112042f;   // log2(e)/8
    const int rA0 = q0 + m0 + g;            // mb=0 rows: rA0, rA0+8
    const int rA1 = rA0 + 16;               // mb=1 rows: rA1, rA1+8

    for (int it = 0; it < nIter; ++it) {
        const int s0 = tile_of(it) * ST;
        const int buf = it & 1;

        CP_WAIT0();
        __syncthreads();

        if (it + 1 < nIter) issue_tile(tile_of(it + 1), buf ^ 1);

        const uint32_t bK = sb + SM_KV0 + buf * KVBUF + boff;
        const uint32_t bV = sb + SM_KV0 + buf * KVBUF + VOFF + voff;
        const bool interior = (s0 + ST <= P);

#pragma unroll
        for (int jp = 0; jp < 4; jp++) {
            // ---- GEMM1 chunk: 16 score columns x 32 rows ----
            float sc[2][2][4];
#pragma unroll
            for (int mb = 0; mb < 2; mb++)
#pragma unroll
                for (int h = 0; h < 2; h++)
#pragma unroll
                    for (int e = 0; e < 4; e++) sc[mb][h][e] = 0.0f;
            const uint32_t ka = bK + jp * (16 * PITCHB);
#pragma unroll
            for (int kk = 0; kk < 4; kk++) {
                uint32_t bh[4];
                LDSM_X4(bh, ka + kk * 32);
                mma_f16(sc[0][0], qh[0][kk], bh);
                mma_f16(sc[1][0], qh[1][kk], bh);
                mma_f16(sc[0][1], qh[0][kk], bh + 2);
                mma_f16(sc[1][1], qh[1][kk], bh + 2);
            }

            // ---- softmax chunk -> P fragments (both M-blocks) ----
            uint32_t af[2][4];
            if (interior) {
#pragma unroll
                for (int mb = 0; mb < 2; mb++) {
                    af[mb][0] = exp2_pair(sc[mb][0][0] * C, sc[mb][0][1] * C);
                    af[mb][1] = exp2_pair(sc[mb][0][2] * C, sc[mb][0][3] * C);
                    af[mb][2] = exp2_pair(sc[mb][1][0] * C, sc[mb][1][1] * C);
                    af[mb][3] = exp2_pair(sc[mb][1][2] * C, sc[mb][1][3] * C);
                }
            } else {
                const int cb0 = s0 + (2 * jp) * 8 + tg * 2;
                const int cb1 = cb0 + 8;
                const bool p00 = (cb0 < P),     p01 = (cb0 + 1 < P);
                const bool p10 = (cb1 < P),     p11 = (cb1 + 1 < P);
#pragma unroll
                for (int mb = 0; mb < 2; mb++) {
                    const int ra = (mb == 0) ? rA0 : rA1;
                    const int rb = ra + 8;
                    const float a0 = (p00 || cb0 == ra)     ? sc[mb][0][0] * C : -1e30f;
                    const float a1 = (p01 || cb0 + 1 == ra) ? sc[mb][0][1] * C : -1e30f;
                    const float a2 = (p00 || cb0 == rb)     ? sc[mb][0][2] * C : -1e30f;
                    const float a3 = (p01 || cb0 + 1 == rb) ? sc[mb][0][3] * C : -1e30f;
                    af[mb][0] = exp2_pair(a0, a1);
                    af[mb][1] = exp2_pair(a2, a3);
                    const float b0 = (p10 || cb1 == ra)     ? sc[mb][1][0] * C : -1e30f;
                    const float b1 = (p11 || cb1 + 1 == ra) ? sc[mb][1][1] * C : -1e30f;
                    const float b2 = (p10 || cb1 == rb)     ? sc[mb][1][2] * C : -1e30f;
                    const float b3 = (p11 || cb1 + 1 == rb) ? sc[mb][1][3] * C : -1e30f;
                    af[mb][2] = exp2_pair(b0, b1);
                    af[mb][3] = exp2_pair(b2, b3);
                }
            }

            // ---- GEMM2 chunk: O += P @ V; l += P @ ones ----
            mma_f16(lacc[0], af[0], bo);
            mma_f16(lacc[1], af[1], bo);
#pragma unroll
            for (int jp2 = 0; jp2 < 4; jp2++) {
                const uint32_t va = bV + jp * (16 * PITCHB) + jp2 * 32;
                uint32_t vh[4];
                LDSM_X4T(vh, va);
                mma_f16(oacc[0][2 * jp2],     af[0], vh);
                mma_f16(oacc[1][2 * jp2],     af[1], vh);
                mma_f16(oacc[0][2 * jp2 + 1], af[0], vh + 2);
                mma_f16(oacc[1][2 * jp2 + 1], af[1], vh + 2);
            }
        }
    }

    // ---- write fp16 partials + fp32 l (4 rows per thread) ----
    if (tg == 0) {
        g_l[sp][n * SEQ + rA0]     = lacc[0][0];
        g_l[sp][n * SEQ + rA0 + 8] = lacc[0][2];
        g_l[sp][n * SEQ + rA1]     = lacc[1][0];
        g_l[sp][n * SEQ + rA1 + 8] = lacc[1][2];
    }
    __half* scr = g_scr[sp];
#pragma unroll
    for (int mb = 0; mb < 2; mb++) {
        const int ra = (mb == 0) ? rA0 : rA1;
#pragma unroll
        for (int j = 0; j < 8; j++) {
            const int col = j * 8 + tg * 2;
            *(uint32_t*)(scr + (size_t)(n * SEQ + ra) * DH + col) =
                pack2h(oacc[mb][j][0], oacc[mb][j][1]);
            *(uint32_t*)(scr + (size_t)(n * SEQ + ra + 8) * DH + col) =
                pack2h(oacc[mb][j][2], oacc[mb][j][3]);
        }
    }
}

// ---- combine: 2 same-row float4 groups per thread; l loaded once ----
__global__ __launch_bounds__(256, 8)
void combine_kernel(float* __restrict__ O) {
    const int t = blockIdx.x * 256 + threadIdx.x;   // 0..131071
    const int i0 = t * 2;                           // float4 group pair (same row)
    const int row = i0 >> 4;
    float l = 0.0f;
    float4 a = make_float4(0.f, 0.f, 0.f, 0.f);
    float4 b = make_float4(0.f, 0.f, 0.f, 0.f);
#pragma unroll
    for (int s = 0; s < KS; s++) {
        const uint4 u = *(const uint4*)&((const uint2*)g_scr[s])[i0];
        const __half2 p0 = *reinterpret_cast<const __half2*>(&u.x);
        const __half2 p1 = *reinterpret_cast<const __half2*>(&u.y);
        const __half2 p2 = *reinterpret_cast<const __half2*>(&u.z);
        const __half2 p3 = *reinterpret_cast<const __half2*>(&u.w);
        a.x += __low2float(p0);  a.y += __high2float(p0);
        a.z += __low2float(p1);  a.w += __high2float(p1);
        b.x += __low2float(p2);  b.y += __high2float(p2);
        b.z += __low2float(p3);  b.w += __high2float(p3);
        l += g_l[s][row];
    }
    const float inv = 1.0f / l;
    ((float4*)O)[i0]     = make_float4(a.x * inv, a.y * inv, a.z * inv, a.w * inv);
    ((float4*)O)[i0 + 1] = make_float4(b.x * inv, b.y * inv, b.z * inv, b.w * inv);
}

extern "C" void kernel_launch(void* const* d_in, const int* in_sizes, int n_in,
                              void* d_out, int out_size) {
    const float* Q      = (const float*)d_in[0];
    const float* K      = (const float*)d_in[1];
    const float* V      = (const float*)d_in[2];
    const int*   prefix = (const int*)d_in[3];
    float*       O      = (float*)d_out;

    prep_kernel<<<dim3(128, 8), 128>>>(K, V);
    cudaFuncSetAttribute(attn_part_kernel,
                         cudaFuncAttributeMaxDynamicSharedMemorySize, SM_TOTAL);
    attn_part_kernel<<<dim3(16 * 8 * KS, 1, 1), 128, SM_TOTAL>>>(Q, prefix);
    combine_kernel<<<(8 * SEQ * DH / 8) / 256, 256>>>(O);
}